// round 1
// baseline (speedup 1.0000x reference)
#include <cuda_runtime.h>
#include <cstdint>

#define HH 1024
#define WW 1024
#define WPR 32          // 32-bit words per bitmap row
#define MAXN 1024

// Scratch (no allocations allowed)
__device__ uint32_t g_bits[HH * WPR];   // 128 KB bitmap of hd_map != 0
__device__ float    g_loss[MAXN];       // per-point loss

// ---------------------------------------------------------------------------
// Kernel 1: pack hd_map (f32 0/1) into a bitmask via warp ballot (coalesced).
// ---------------------------------------------------------------------------
__global__ void pack_kernel(const float* __restrict__ map) {
    int idx = blockIdx.x * blockDim.x + threadIdx.x;   // < HH*WW
    uint32_t b = __ballot_sync(0xFFFFFFFFu, map[idx] != 0.0f);
    if ((threadIdx.x & 31) == 0) g_bits[idx >> 5] = b;
}

__device__ __forceinline__ int bit_at(int r, int c) {
    r = min(max(r, 0), HH - 1);
    c = min(max(c, 0), WW - 1);
    return (int)((g_bits[r * WPR + (c >> 5)] >> (c & 31)) & 1u);
}

// ---------------------------------------------------------------------------
// Kernel 2: one CTA per point. Thread = one map row. Find nearest set/clear
// column to p1 in that row (clz/ffs outward scan), combine with (r-p0)^2,
// block-min-reduce (exact integer arithmetic), lane0 computes the loss.
// ---------------------------------------------------------------------------
__global__ void __launch_bounds__(1024) point_kernel(const int* __restrict__ pred) {
    const int i  = blockIdx.x;
    const int p0 = pred[2 * i];
    const int p1 = pred[2 * i + 1];

    // outside_frame uses strict > H / > W (matches reference)
    const bool outside_frame = (p0 < 0) | (p0 > HH) | (p1 < 0) | (p1 > WW);
    if (outside_frame) {
        if (threadIdx.x == 0) g_loss[i] = 0.0f;
        return;
    }

    const int r = threadIdx.x;                 // row handled by this thread
    const uint32_t* rw = g_bits + r * WPR;
    const int BIG = 1 << 20;
    int dsl = BIG, dsr = BIG, dcl = BIG, dcr = BIG;   // set/clear, left/right

    // ---- left scan: columns <= p1 ----
    {
        int pcl = min(p1, WW - 1);
        int w = pcl >> 5, b = pcl & 31;
        uint32_t mask = 0xFFFFFFFFu >> (31 - b);
        bool nS = true, nC = true;
        for (int ww = w; ww >= 0 && (nS | nC); --ww) {
            uint32_t word = rw[ww];
            uint32_t ms = word, mc = ~word;
            if (ww == w) { ms &= mask; mc &= mask; }
            if (nS && ms) { dsl = p1 - ((ww << 5) + 31 - __clz(ms)); nS = false; }
            if (nC && mc) { dcl = p1 - ((ww << 5) + 31 - __clz(mc)); nC = false; }
        }
    }
    // ---- right scan: columns >= p1 ----
    if (p1 <= WW - 1) {
        int w = p1 >> 5, b = p1 & 31;
        uint32_t mask = 0xFFFFFFFFu << b;
        bool nS = true, nC = true;
        for (int ww = w; ww < WPR && (nS | nC); ++ww) {
            uint32_t word = rw[ww];
            uint32_t ms = word, mc = ~word;
            if (ww == w) { ms &= mask; mc &= mask; }
            if (nS && ms) { dsr = ((ww << 5) + __ffs(ms) - 1) - p1; nS = false; }
            if (nC && mc) { dcr = ((ww << 5) + __ffs(mc) - 1) - p1; nC = false; }
        }
    }

    int ds  = min(dsl, dsr);                   // nearest road(=1) column dist
    int dc  = min(dcl, dcr);                   // nearest non-road column dist
    int dr2 = (r - p0) * (r - p0);
    int cand_nd = (ds < 2048) ? dr2 + ds * ds : 0x7FFFFFFF;
    int cand_dr = (dc < 2048) ? dr2 + dc * dc : 0x7FFFFFFF;

    // ---- block min-reduce over 1024 threads (32 warps) ----
    __shared__ int snd[32], sdrr[32];
    cand_nd = __reduce_min_sync(0xFFFFFFFFu, cand_nd);
    cand_dr = __reduce_min_sync(0xFFFFFFFFu, cand_dr);
    const int lane = threadIdx.x & 31, wid = threadIdx.x >> 5;
    if (lane == 0) { snd[wid] = cand_nd; sdrr[wid] = cand_dr; }
    __syncthreads();
    if (wid == 0) {
        int a = __reduce_min_sync(0xFFFFFFFFu, snd[lane]);
        int b = __reduce_min_sync(0xFFFFFFFFu, sdrr[lane]);
        if (lane == 0) {
            // outside_road: replicate reference's validity masks exactly
            const bool rvm1 = (p0 >= 1);
            const bool rv0  = (p0 >= 1) && (p0 < HH);
            const bool cvm1 = (p1 >= 1);
            const bool cv0  = (p1 >= 1) && (p1 < WW);
            const bool outside_road =
                (rvm1 && cvm1 && bit_at(p0 - 1, p1 - 1)) ||
                (rvm1 && cv0  && bit_at(p0 - 1, p1    )) ||
                (rv0  && cvm1 && bit_at(p0,     p1 - 1)) ||
                (rv0  && cv0  && bit_at(p0,     p1    ));
            float L;
            if (outside_road) {
                // exp(sqrt(min_dr) * ln2 / 40) - 1  ==  2^(sqrt(min_dr)/40) - 1
                L = exp2f(sqrtf((float)b) * (1.0f / 40.0f)) - 1.0f;
            } else {
                L = expf(-(float)a * (1.0f / 21.7f));
            }
            g_loss[i] = L;
        }
    }
}

// ---------------------------------------------------------------------------
// Kernel 3: deterministic fixed-order reduction -> mean
// ---------------------------------------------------------------------------
__global__ void finalize_kernel(float* __restrict__ out, int N) {
    float v = 0.0f;
    for (int t = threadIdx.x; t < N; t += blockDim.x) v += g_loss[t];
#pragma unroll
    for (int o = 16; o; o >>= 1) v += __shfl_down_sync(0xFFFFFFFFu, v, o);
    __shared__ float ws[32];
    const int lane = threadIdx.x & 31, wid = threadIdx.x >> 5;
    if (lane == 0) ws[wid] = v;
    __syncthreads();
    if (threadIdx.x == 0) {
        float s = 0.0f;
        int nw = (blockDim.x + 31) >> 5;
        for (int w = 0; w < nw; ++w) s += ws[w];
        out[0] = s / (float)N;
    }
}

extern "C" void kernel_launch(void* const* d_in, const int* in_sizes, int n_in,
                              void* d_out, int out_size) {
    const float* hd_map = (const float*)d_in[0];
    const int*   pred   = (const int*)d_in[1];
    float*       out    = (float*)d_out;
    const int N = in_sizes[1] / 2;

    pack_kernel<<<(HH * WW) / 256, 256>>>(hd_map);
    point_kernel<<<N, 1024>>>(pred);
    finalize_kernel<<<1, 128>>>(out, N);
}

// round 3
// speedup vs baseline: 1.1114x; 1.1114x over previous
#include <cuda_runtime.h>
#include <cstdint>

#define HH 1024
#define WW 1024
#define WPR 32          // 32-bit words per bitmap row
#define MAXN 1024

// Scratch (no allocations allowed)
__device__ uint32_t g_bits[HH * WPR];   // 128 KB bitmap of hd_map != 0
__device__ float    g_loss[MAXN];       // per-point loss
__device__ unsigned g_cnt;              // completion counter for last-block finalize

// ---------------------------------------------------------------------------
// Kernel 1: pack hd_map (f32 0/1) into a bitmask.
// float4 loads, 4 independent loads per thread (MLP=4), shuffle-XOR packing.
// Also resets the completion counter for this replay.
// ---------------------------------------------------------------------------
#define PACK_BLOCKS  256
#define PACK_THREADS 256
#define PACK_UNROLL  4
// total float4 elements = HH*WW/4 = 262144 = PACK_BLOCKS*PACK_THREADS*PACK_UNROLL

__global__ void __launch_bounds__(PACK_THREADS) pack_kernel(const float4* __restrict__ m4) {
    if (blockIdx.x == 0 && threadIdx.x == 0) g_cnt = 0u;

    const int t      = blockIdx.x * PACK_THREADS + threadIdx.x;
    const int stride = PACK_BLOCKS * PACK_THREADS;   // 65536

    float4 v[PACK_UNROLL];
#pragma unroll
    for (int u = 0; u < PACK_UNROLL; ++u) v[u] = m4[t + u * stride];

    const int lane = threadIdx.x & 31;
    const uint32_t sh = (uint32_t)((lane & 7) * 4);
#pragma unroll
    for (int u = 0; u < PACK_UNROLL; ++u) {
        uint32_t nib = (uint32_t)(v[u].x != 0.0f)
                     | ((uint32_t)(v[u].y != 0.0f) << 1)
                     | ((uint32_t)(v[u].z != 0.0f) << 2)
                     | ((uint32_t)(v[u].w != 0.0f) << 3);
        uint32_t b = nib << sh;
        b |= __shfl_xor_sync(0xFFFFFFFFu, b, 1);
        b |= __shfl_xor_sync(0xFFFFFFFFu, b, 2);
        b |= __shfl_xor_sync(0xFFFFFFFFu, b, 4);
        if ((lane & 7) == 0) g_bits[(t + u * stride) >> 3] = b;
    }
}

__device__ __forceinline__ int bit_at(int r, int c) {
    r = min(max(r, 0), HH - 1);
    c = min(max(c, 0), WW - 1);
    return (int)((g_bits[r * WPR + (c >> 5)] >> (c & 31)) & 1u);
}

// ---------------------------------------------------------------------------
// Kernel 2: one CTA per point + fused last-block finalize.
// ---------------------------------------------------------------------------
__global__ void __launch_bounds__(1024) point_kernel(const int* __restrict__ pred,
                                                     float* __restrict__ out,
                                                     int N) {
    const int i  = blockIdx.x;
    const int p0 = __ldg(&pred[2 * i]);
    const int p1 = __ldg(&pred[2 * i + 1]);

    // outside_frame uses strict > H / > W (matches reference)
    const bool outside_frame = (p0 < 0) | (p0 > HH) | (p1 < 0) | (p1 > WW);
    float L = 0.0f;   // meaningful in thread 0 only

    if (!outside_frame) {   // block-uniform branch
        const int r = threadIdx.x;                 // row handled by this thread
        const uint32_t* rw = g_bits + r * WPR;
        const int BIG = 1 << 20;
        int dsl = BIG, dsr = BIG, dcl = BIG, dcr = BIG;   // set/clear, left/right

        // ---- left scan: columns <= p1 ----
        {
            int pcl = min(p1, WW - 1);
            int w = pcl >> 5, b = pcl & 31;
            uint32_t mask = 0xFFFFFFFFu >> (31 - b);
            bool nS = true, nC = true;
            for (int ww = w; ww >= 0 && (nS | nC); --ww) {
                uint32_t word = rw[ww];
                uint32_t ms = word, mc = ~word;
                if (ww == w) { ms &= mask; mc &= mask; }
                if (nS && ms) { dsl = p1 - ((ww << 5) + 31 - __clz(ms)); nS = false; }
                if (nC && mc) { dcl = p1 - ((ww << 5) + 31 - __clz(mc)); nC = false; }
            }
        }
        // ---- right scan: columns >= p1 ----
        if (p1 <= WW - 1) {
            int w = p1 >> 5, b = p1 & 31;
            uint32_t mask = 0xFFFFFFFFu << b;
            bool nS = true, nC = true;
            for (int ww = w; ww < WPR && (nS | nC); ++ww) {
                uint32_t word = rw[ww];
                uint32_t ms = word, mc = ~word;
                if (ww == w) { ms &= mask; mc &= mask; }
                if (nS && ms) { dsr = ((ww << 5) + __ffs(ms) - 1) - p1; nS = false; }
                if (nC && mc) { dcr = ((ww << 5) + __ffs(mc) - 1) - p1; nC = false; }
            }
        }

        int ds  = min(dsl, dsr);                   // nearest road(=1) column dist
        int dc  = min(dcl, dcr);                   // nearest non-road column dist
        int dr2 = (r - p0) * (r - p0);
        int cand_nd = (ds < 2048) ? dr2 + ds * ds : 0x7FFFFFFF;
        int cand_dr = (dc < 2048) ? dr2 + dc * dc : 0x7FFFFFFF;

        // ---- block min-reduce over 1024 threads (32 warps) ----
        __shared__ int snd[32], sdrr[32];
        cand_nd = __reduce_min_sync(0xFFFFFFFFu, cand_nd);
        cand_dr = __reduce_min_sync(0xFFFFFFFFu, cand_dr);
        const int lane = threadIdx.x & 31, wid = threadIdx.x >> 5;
        if (lane == 0) { snd[wid] = cand_nd; sdrr[wid] = cand_dr; }
        __syncthreads();
        int a = 0, b = 0;
        if (wid == 0) {
            a = __reduce_min_sync(0xFFFFFFFFu, snd[lane]);
            b = __reduce_min_sync(0xFFFFFFFFu, sdrr[lane]);
        }
        if (threadIdx.x == 0) {
            // outside_road: replicate reference's validity masks exactly
            const bool rvm1 = (p0 >= 1);
            const bool rv0  = (p0 >= 1) && (p0 < HH);
            const bool cvm1 = (p1 >= 1);
            const bool cv0  = (p1 >= 1) && (p1 < WW);
            const bool outside_road =
                (rvm1 && cvm1 && bit_at(p0 - 1, p1 - 1)) ||
                (rvm1 && cv0  && bit_at(p0 - 1, p1    )) ||
                (rv0  && cvm1 && bit_at(p0,     p1 - 1)) ||
                (rv0  && cv0  && bit_at(p0,     p1    ));
            if (outside_road) {
                // exp(sqrt(min_dr) * ln2 / 40) - 1  ==  2^(sqrt(min_dr)/40) - 1
                L = exp2f(sqrtf((float)b) * (1.0f / 40.0f)) - 1.0f;
            } else {
                L = expf(-(float)a * (1.0f / 21.7f));
            }
        }
    }

    // ---- publish per-point loss, detect last block ----
    __shared__ bool isLast;
    if (threadIdx.x == 0) {
        g_loss[i] = L;
        __threadfence();
        unsigned prev = atomicAdd(&g_cnt, 1u);
        isLast = (prev == (unsigned)(gridDim.x - 1));
    }
    __syncthreads();

    // ---- last block: deterministic fixed-order reduction -> mean ----
    if (isLast) {
        float v = (threadIdx.x < N) ? g_loss[threadIdx.x] : 0.0f;
#pragma unroll
        for (int o = 16; o; o >>= 1) v += __shfl_down_sync(0xFFFFFFFFu, v, o);
        __shared__ float ws[32];
        const int lane = threadIdx.x & 31, wid = threadIdx.x >> 5;
        if (lane == 0) ws[wid] = v;
        __syncthreads();
        if (threadIdx.x == 0) {
            float s = 0.0f;
#pragma unroll
            for (int w = 0; w < 32; ++w) s += ws[w];
            out[0] = s / (float)N;
        }
    }
}

extern "C" void kernel_launch(void* const* d_in, const int* in_sizes, int n_in,
                              void* d_out, int out_size) {
    const float* hd_map = (const float*)d_in[0];
    const int*   pred   = (const int*)d_in[1];
    float*       out    = (float*)d_out;
    const int N = in_sizes[1] / 2;

    pack_kernel<<<PACK_BLOCKS, PACK_THREADS>>>((const float4*)hd_map);
    point_kernel<<<N, 1024>>>(pred, out, N);
}

// round 6
// speedup vs baseline: 1.2118x; 1.0903x over previous
#include <cuda_runtime.h>
#include <cstdint>

#define HH 1024
#define WW 1024
#define WPR 32          // 32-bit words per bitmap row
#define MAXN 1024

// Scratch (no allocations allowed).
// TRANSPOSED bitmap: g_bits_T[w * HH + r] holds bits for columns [32w,32w+31] of row r.
// A warp (consecutive r, same w) reads one contiguous 128B line -> coalesced.
__device__ uint32_t g_bits_T[WPR * HH];  // 128 KB
__device__ float    g_loss[MAXN];        // per-point loss
__device__ unsigned g_cnt;               // completion counter for last-block finalize

// ---------------------------------------------------------------------------
// Kernel 1: pack hd_map (f32 0/1) into the transposed bitmask.
// float4 loads, 4 independent loads per thread (MLP=4), shuffle-XOR packing.
// Also resets the completion counter for this replay.
// ---------------------------------------------------------------------------
#define PACK_BLOCKS  256
#define PACK_THREADS 256
#define PACK_UNROLL  4
// total float4 elements = HH*WW/4 = 262144 = PACK_BLOCKS*PACK_THREADS*PACK_UNROLL

__global__ void __launch_bounds__(PACK_THREADS) pack_kernel(const float4* __restrict__ m4) {
    if (blockIdx.x == 0 && threadIdx.x == 0) g_cnt = 0u;

    const int t      = blockIdx.x * PACK_THREADS + threadIdx.x;
    const int stride = PACK_BLOCKS * PACK_THREADS;   // 65536

    float4 v[PACK_UNROLL];
#pragma unroll
    for (int u = 0; u < PACK_UNROLL; ++u) v[u] = m4[t + u * stride];

    const int lane = threadIdx.x & 31;
    const uint32_t sh = (uint32_t)((lane & 7) * 4);
#pragma unroll
    for (int u = 0; u < PACK_UNROLL; ++u) {
        uint32_t nib = (uint32_t)(v[u].x != 0.0f)
                     | ((uint32_t)(v[u].y != 0.0f) << 1)
                     | ((uint32_t)(v[u].z != 0.0f) << 2)
                     | ((uint32_t)(v[u].w != 0.0f) << 3);
        uint32_t b = nib << sh;
        b |= __shfl_xor_sync(0xFFFFFFFFu, b, 1);
        b |= __shfl_xor_sync(0xFFFFFFFFu, b, 2);
        b |= __shfl_xor_sync(0xFFFFFFFFu, b, 4);
        if ((lane & 7) == 0) {
            int idx32 = (t + u * stride) >> 3;     // word index in row-major order
            int r = idx32 >> 5;                    // row
            int w = idx32 & 31;                    // word-column
            g_bits_T[w * HH + r] = b;              // transposed store
        }
    }
}

__device__ __forceinline__ int bit_at(int r, int c) {
    r = min(max(r, 0), HH - 1);
    c = min(max(c, 0), WW - 1);
    return (int)((g_bits_T[(c >> 5) * HH + r] >> (c & 31)) & 1u);
}

// ---------------------------------------------------------------------------
// Kernel 2: one CTA per point + fused last-block finalize.
// Thread = one map row; outward clz/ffs scan over transposed (coalesced) words.
// ---------------------------------------------------------------------------
__global__ void __launch_bounds__(1024) point_kernel(const int* __restrict__ pred,
                                                     float* __restrict__ out,
                                                     int N) {
    const int i  = blockIdx.x;
    const int p0 = __ldg(&pred[2 * i]);
    const int p1 = __ldg(&pred[2 * i + 1]);

    // outside_frame uses strict > H / > W (matches reference)
    const bool outside_frame = (p0 < 0) | (p0 > HH) | (p1 < 0) | (p1 > WW);
    float L = 0.0f;   // meaningful in thread 0 only

    if (!outside_frame) {   // block-uniform branch
        const int r = threadIdx.x;                 // row handled by this thread
        const int BIG = 1 << 20;
        int dsl = BIG, dsr = BIG, dcl = BIG, dcr = BIG;   // set/clear, left/right

        // ---- left scan: columns <= p1 ----
        {
            int pcl = min(p1, WW - 1);
            int w = pcl >> 5, b = pcl & 31;
            uint32_t mask = 0xFFFFFFFFu >> (31 - b);
            bool nS = true, nC = true;
            for (int ww = w; ww >= 0 && (nS | nC); --ww) {
                uint32_t word = g_bits_T[ww * HH + r];
                uint32_t ms = word, mc = ~word;
                if (ww == w) { ms &= mask; mc &= mask; }
                if (nS && ms) { dsl = p1 - ((ww << 5) + 31 - __clz(ms)); nS = false; }
                if (nC && mc) { dcl = p1 - ((ww << 5) + 31 - __clz(mc)); nC = false; }
            }
        }
        // ---- right scan: columns >= p1 ----
        if (p1 <= WW - 1) {
            int w = p1 >> 5, b = p1 & 31;
            uint32_t mask = 0xFFFFFFFFu << b;
            bool nS = true, nC = true;
            for (int ww = w; ww < WPR && (nS | nC); ++ww) {
                uint32_t word = g_bits_T[ww * HH + r];
                uint32_t ms = word, mc = ~word;
                if (ww == w) { ms &= mask; mc &= mask; }
                if (nS && ms) { dsr = ((ww << 5) + __ffs(ms) - 1) - p1; nS = false; }
                if (nC && mc) { dcr = ((ww << 5) + __ffs(mc) - 1) - p1; nC = false; }
            }
        }

        int ds  = min(dsl, dsr);                   // nearest road(=1) column dist
        int dc  = min(dcl, dcr);                   // nearest non-road column dist
        int dr2 = (r - p0) * (r - p0);
        int cand_nd = (ds < 2048) ? dr2 + ds * ds : 0x7FFFFFFF;
        int cand_dr = (dc < 2048) ? dr2 + dc * dc : 0x7FFFFFFF;

        // ---- block min-reduce over 1024 threads (32 warps) ----
        __shared__ int snd[32], sdrr[32];
        cand_nd = __reduce_min_sync(0xFFFFFFFFu, cand_nd);
        cand_dr = __reduce_min_sync(0xFFFFFFFFu, cand_dr);
        const int lane = threadIdx.x & 31, wid = threadIdx.x >> 5;
        if (lane == 0) { snd[wid] = cand_nd; sdrr[wid] = cand_dr; }
        __syncthreads();
        int a = 0, b = 0;
        if (wid == 0) {
            a = __reduce_min_sync(0xFFFFFFFFu, snd[lane]);
            b = __reduce_min_sync(0xFFFFFFFFu, sdrr[lane]);
        }
        if (threadIdx.x == 0) {
            // outside_road: replicate reference's validity masks exactly
            const bool rvm1 = (p0 >= 1);
            const bool rv0  = (p0 >= 1) && (p0 < HH);
            const bool cvm1 = (p1 >= 1);
            const bool cv0  = (p1 >= 1) && (p1 < WW);
            const bool outside_road =
                (rvm1 && cvm1 && bit_at(p0 - 1, p1 - 1)) ||
                (rvm1 && cv0  && bit_at(p0 - 1, p1    )) ||
                (rv0  && cvm1 && bit_at(p0,     p1 - 1)) ||
                (rv0  && cv0  && bit_at(p0,     p1    ));
            if (outside_road) {
                // exp(sqrt(min_dr) * ln2 / 40) - 1  ==  2^(sqrt(min_dr)/40) - 1
                L = exp2f(sqrtf((float)b) * (1.0f / 40.0f)) - 1.0f;
            } else {
                L = expf(-(float)a * (1.0f / 21.7f));
            }
        }
    }

    // ---- publish per-point loss, detect last block ----
    __shared__ bool isLast;
    if (threadIdx.x == 0) {
        g_loss[i] = L;
        __threadfence();
        unsigned prev = atomicAdd(&g_cnt, 1u);
        isLast = (prev == (unsigned)(gridDim.x - 1));
    }
    __syncthreads();

    // ---- last block: deterministic fixed-order reduction -> mean ----
    if (isLast) {
        float v = (threadIdx.x < N) ? g_loss[threadIdx.x] : 0.0f;
#pragma unroll
        for (int o = 16; o; o >>= 1) v += __shfl_down_sync(0xFFFFFFFFu, v, o);
        __shared__ float ws[32];
        const int lane = threadIdx.x & 31, wid = threadIdx.x >> 5;
        if (lane == 0) ws[wid] = v;
        __syncthreads();
        if (threadIdx.x == 0) {
            float s = 0.0f;
#pragma unroll
            for (int w = 0; w < 32; ++w) s += ws[w];
            out[0] = s / (float)N;
        }
    }
}

extern "C" void kernel_launch(void* const* d_in, const int* in_sizes, int n_in,
                              void* d_out, int out_size) {
    const float* hd_map = (const float*)d_in[0];
    const int*   pred   = (const int*)d_in[1];
    float*       out    = (float*)d_out;
    const int N = in_sizes[1] / 2;

    pack_kernel<<<PACK_BLOCKS, PACK_THREADS>>>((const float4*)hd_map);
    point_kernel<<<N, 1024>>>(pred, out, N);
}